// round 3
// baseline (speedup 1.0000x reference)
#include <cuda_runtime.h>

#define Bc 4
#define Sc 1024
#define Dc 512
#define Hc 8
#define DHc 64

// ---- scratch (no allocations allowed) ----
__device__ float g_Q[Bc*Hc*Sc*DHc];   // [B,H,S,DH]
__device__ float g_K[Bc*Hc*Sc*DHc];
__device__ float g_V[Bc*Hc*Sc*DHc];
__device__ float g_ctx[Bc*Sc*Dc];     // [B,S,D]

// ============================================================
// GEMM: out = A[M,512] @ W[512,512]; optional head-split store
// block tile 64x64, K-step 16, 256 threads, 4x4 per thread
// ============================================================
__global__ __launch_bounds__(256) void gemm512(const float* __restrict__ A,
                                               const float* __restrict__ W,
                                               float* __restrict__ out,
                                               int headsplit) {
    __shared__ float As[16][65];   // [k][m] transposed
    __shared__ float Bs[16][68];   // [k][n]
    const int tid = threadIdx.x;
    const int tx = tid & 15, ty = tid >> 4;
    const int m0 = blockIdx.y << 6, n0 = blockIdx.x << 6;

    const int ar  = tid >> 2;            // 0..63  (row in A tile)
    const int ak4 = (tid & 3) << 2;      // 0,4,8,12
    const int wk  = tid >> 4;            // 0..15
    const int wn4 = (tid & 15) << 2;     // 0..60

    float acc[4][4] = {};

    for (int k0 = 0; k0 < 512; k0 += 16) {
        float4 av = *(const float4*)(A + (size_t)(m0 + ar) * 512 + k0 + ak4);
        As[ak4+0][ar] = av.x; As[ak4+1][ar] = av.y;
        As[ak4+2][ar] = av.z; As[ak4+3][ar] = av.w;
        float4 wv = *(const float4*)(W + (size_t)(k0 + wk) * 512 + n0 + wn4);
        *(float4*)&Bs[wk][wn4] = wv;
        __syncthreads();
#pragma unroll
        for (int kk = 0; kk < 16; kk++) {
            float a[4];
            a[0] = As[kk][ty*4+0]; a[1] = As[kk][ty*4+1];
            a[2] = As[kk][ty*4+2]; a[3] = As[kk][ty*4+3];
            float4 bv = *(float4*)&Bs[kk][tx*4];
            float b[4] = {bv.x, bv.y, bv.z, bv.w};
#pragma unroll
            for (int i = 0; i < 4; i++)
#pragma unroll
                for (int j = 0; j < 4; j++)
                    acc[i][j] += a[i] * b[j];
        }
        __syncthreads();
    }

    if (headsplit) {
        const int hh = n0 >> 6;   // head index (n0 is multiple of 64)
#pragma unroll
        for (int i = 0; i < 4; i++) {
            int m = m0 + ty*4 + i;
            int bb = m >> 10, s = m & 1023;
            float4 o = make_float4(acc[i][0], acc[i][1], acc[i][2], acc[i][3]);
            *(float4*)&out[((size_t)(bb*Hc + hh) * Sc + s) * DHc + tx*4] = o;
        }
    } else {
#pragma unroll
        for (int i = 0; i < 4; i++) {
            int m = m0 + ty*4 + i;
            float4 o = make_float4(acc[i][0], acc[i][1], acc[i][2], acc[i][3]);
            *(float4*)&out[(size_t)m * 512 + n0 + tx*4] = o;
        }
    }
}

// ============================================================
// Fused causal attention with skewed relative bias.
// bias[j,t] = sum_d q[j,d] * R[h][d][S-1-j+t]   (t <= j)
// One CTA per (bh, 64-query tile). Flash-style online softmax
// over 64-key tiles; causal tiles skipped entirely.
// ============================================================
__global__ __launch_bounds__(256) void attn_kernel(const float* __restrict__ Rel) {
    extern __shared__ float sm[];
    float* qs = sm;                 // [d][j]  64x68
    float* ks = qs + 64*68;         // [d][t]  64x68
    float* vs = ks + 64*68;         // [t][d]  64x68
    float* ps = vs + 64*68;         // [j][t]  64x68
    float* rs = ps + 64*68;         // [d][cc] 64x128

    const int tid = threadIdx.x;
    const int tx = tid & 15, ty = tid >> 4;
    const int bh = blockIdx.y;          // b*H + h
    const int h  = bh & (Hc-1);
    const int j0 = blockIdx.x << 6;

    const float* Qp    = g_Q + ((size_t)bh * Sc + j0) * DHc;
    const float* Kbase = g_K + (size_t)bh * Sc * DHc;
    const float* Vbase = g_V + (size_t)bh * Sc * DHc;
    const float* Rp    = Rel + (size_t)h * DHc * Sc;

    // load Q tile -> qs[d][j]
    for (int f = tid; f < 1024; f += 256) {
        int j = f >> 4, d4 = (f & 15) << 2;
        float4 v = *(const float4*)(Qp + j*DHc + d4);
        qs[(d4+0)*68 + j] = v.x; qs[(d4+1)*68 + j] = v.y;
        qs[(d4+2)*68 + j] = v.z; qs[(d4+3)*68 + j] = v.w;
    }

    float mrow[4] = {-1e30f, -1e30f, -1e30f, -1e30f};
    float lrow[4] = {0.f, 0.f, 0.f, 0.f};
    float oacc[4][4] = {};

    const int base0 = 60 + 4*tx - 4*ty;   // r-window base: in [0,120], mult of 4
    const int ntiles = (j0 >> 6) + 1;

    for (int it = 0; it < ntiles; it++) {
        const int t0 = it << 6;
        __syncthreads();   // protect ks/vs/rs (and ps from previous PV read)

        // load K,V tiles
        for (int f = tid; f < 1024; f += 256) {
            int t = f >> 4, d4 = (f & 15) << 2;
            float4 kv = *(const float4*)(Kbase + (size_t)(t0 + t)*DHc + d4);
            ks[(d4+0)*68 + t] = kv.x; ks[(d4+1)*68 + t] = kv.y;
            ks[(d4+2)*68 + t] = kv.z; ks[(d4+3)*68 + t] = kv.w;
            float4 vv = *(const float4*)(Vbase + (size_t)(t0 + t)*DHc + d4);
            *(float4*)(vs + t*68 + d4) = vv;
        }
        // load R window: rs[d][cc] = R[d][cmin+cc], 127 cols used
        const int cmin = Sc - 64 - j0 + t0;   // >= 0, multiple of 4
        for (int f = tid; f < 64*32; f += 256) {
            int d = f >> 5, cc4 = (f & 31) << 2;
            int col = cmin + cc4;
            float4 rv4 = (col < Sc) ? *(const float4*)(Rp + (size_t)d*Sc + col)
                                    : make_float4(0.f, 0.f, 0.f, 0.f);
            *(float4*)(rs + d*128 + cc4) = rv4;
        }
        __syncthreads();

        // s[j][t] = q.k + q.R[:, S-1-j+t]
        float acc[4][4] = {};
#pragma unroll 8
        for (int d = 0; d < 64; d++) {
            float4 qv = *(float4*)(qs + d*68 + ty*4);
            float4 kv = *(float4*)(ks + d*68 + tx*4);
            float4 r0 = *(float4*)(rs + d*128 + base0);
            float4 r1 = *(float4*)(rs + d*128 + base0 + 4);
            float qa[4] = {qv.x, qv.y, qv.z, qv.w};
            float ka[4] = {kv.x, kv.y, kv.z, kv.w};
            float ra[8] = {r0.x, r0.y, r0.z, r0.w, r1.x, r1.y, r1.z, r1.w};
#pragma unroll
            for (int i = 0; i < 4; i++)
#pragma unroll
                for (int j = 0; j < 4; j++) {
                    acc[i][j] += qa[i] * ka[j];
                    acc[i][j] += qa[i] * ra[3 - i + j];   // c_local = 63-(jl)+(tl)
                }
        }

        // online softmax (scale AFTER bias+mask, matching reference)
#pragma unroll
        for (int i = 0; i < 4; i++) {
            const int j = j0 + ty*4 + i;
            float mx = -1e30f;
#pragma unroll
            for (int c = 0; c < 4; c++) {
                int t = t0 + tx*4 + c;
                float v = (t <= j) ? acc[i][c] * 0.125f : -1e30f;
                acc[i][c] = v;
                mx = fmaxf(mx, v);
            }
#pragma unroll
            for (int off = 8; off; off >>= 1)
                mx = fmaxf(mx, __shfl_xor_sync(0xffffffffu, mx, off, 16));
            float mnew = fmaxf(mrow[i], mx);
            float corr = __expf(mrow[i] - mnew);
            float ss = 0.f;
#pragma unroll
            for (int c = 0; c < 4; c++) {
                float p = __expf(acc[i][c] - mnew);
                ss += p;
                ps[(ty*4+i)*68 + tx*4 + c] = p;
            }
#pragma unroll
            for (int off = 8; off; off >>= 1)
                ss += __shfl_xor_sync(0xffffffffu, ss, off, 16);
            lrow[i] = lrow[i] * corr + ss;
            mrow[i] = mnew;
#pragma unroll
            for (int c = 0; c < 4; c++) oacc[i][c] *= corr;
        }
        __syncthreads();

        // O += P @ V
#pragma unroll 8
        for (int t = 0; t < 64; t++) {
            float4 vv = *(float4*)(vs + t*68 + tx*4);
            float va[4] = {vv.x, vv.y, vv.z, vv.w};
            float pa[4];
#pragma unroll
            for (int i = 0; i < 4; i++) pa[i] = ps[(ty*4+i)*68 + t];
#pragma unroll
            for (int i = 0; i < 4; i++)
#pragma unroll
                for (int c = 0; c < 4; c++)
                    oacc[i][c] += pa[i] * va[c];
        }
    }

    // epilogue: ctx[b][j][h*64 + dc]
    const int b = bh >> 3;
#pragma unroll
    for (int i = 0; i < 4; i++) {
        float inv = 1.f / lrow[i];
        float4 o = make_float4(oacc[i][0]*inv, oacc[i][1]*inv,
                               oacc[i][2]*inv, oacc[i][3]*inv);
        *(float4*)&g_ctx[((size_t)(b*Sc + j0 + ty*4 + i)) * Dc + h*DHc + tx*4] = o;
    }
}

// ============================================================
extern "C" void kernel_launch(void* const* d_in, const int* in_sizes, int n_in,
                              void* d_out, int out_size) {
    (void)in_sizes; (void)n_in; (void)out_size;
    const float* queries = (const float*)d_in[0];
    const float* keysp   = (const float*)d_in[1];
    const float* valuesp = (const float*)d_in[2];
    // d_in[3] = mask (causal; applied analytically)
    const float* Wq  = (const float*)d_in[4];
    const float* Wk  = (const float*)d_in[5];
    const float* Wv  = (const float*)d_in[6];
    const float* Wo  = (const float*)d_in[7];
    const float* rel = (const float*)d_in[8];
    float* out = (float*)d_out;

    float *pQ, *pK, *pV, *pC;
    cudaGetSymbolAddress((void**)&pQ, g_Q);
    cudaGetSymbolAddress((void**)&pK, g_K);
    cudaGetSymbolAddress((void**)&pV, g_V);
    cudaGetSymbolAddress((void**)&pC, g_ctx);

    const dim3 blk(256);
    const dim3 gproj(Dc/64, (Bc*Sc)/64);   // (8, 64)

    gemm512<<<gproj, blk>>>(queries, Wq, pQ, 1);
    gemm512<<<gproj, blk>>>(keysp,   Wk, pK, 1);
    gemm512<<<gproj, blk>>>(valuesp, Wv, pV, 1);

    const int smem = (4*64*68 + 64*128) * (int)sizeof(float);   // 102400 B
    cudaFuncSetAttribute(attn_kernel, cudaFuncAttributeMaxDynamicSharedMemorySize, smem);
    attn_kernel<<<dim3(Sc/64, Bc*Hc), blk, smem>>>(rel);

    gemm512<<<gproj, blk>>>(pC, Wo, out, 0);
}

// round 6
// speedup vs baseline: 1.0379x; 1.0379x over previous
#include <cuda_runtime.h>

#define Bc 4
#define Sc 1024
#define Dc 512
#define Hc 8
#define DHc 64

// ---- scratch (no allocations allowed) ----
__device__ float g_Q[Bc*Hc*Sc*DHc];   // [B,H,S,DH]
__device__ float g_K[Bc*Hc*Sc*DHc];
__device__ float g_V[Bc*Hc*Sc*DHc];
__device__ float g_ctx[Bc*Sc*Dc];     // [B,S,D]

// ============================================================
// GEMM body: out = A[M,512] @ W[512,512]
// block tile 64x64, K-step 16, 256 threads, 4x4 per thread
// ============================================================
__device__ __forceinline__ void gemm512_body(const float* __restrict__ A,
                                             const float* __restrict__ W,
                                             float* __restrict__ out,
                                             int headsplit) {
    __shared__ float As[16][65];   // [k][m] transposed
    __shared__ float Bs[16][68];   // [k][n]
    const int tid = threadIdx.x;
    const int tx = tid & 15, ty = tid >> 4;
    const int m0 = blockIdx.y << 6, n0 = blockIdx.x << 6;

    const int ar  = tid >> 2;            // 0..63  (row in A tile)
    const int ak4 = (tid & 3) << 2;      // 0,4,8,12
    const int wk  = tid >> 4;            // 0..15
    const int wn4 = (tid & 15) << 2;     // 0..60

    float acc[4][4] = {};

    for (int k0 = 0; k0 < 512; k0 += 16) {
        float4 av = *(const float4*)(A + (size_t)(m0 + ar) * 512 + k0 + ak4);
        As[ak4+0][ar] = av.x; As[ak4+1][ar] = av.y;
        As[ak4+2][ar] = av.z; As[ak4+3][ar] = av.w;
        float4 wv = *(const float4*)(W + (size_t)(k0 + wk) * 512 + n0 + wn4);
        *(float4*)&Bs[wk][wn4] = wv;
        __syncthreads();
#pragma unroll
        for (int kk = 0; kk < 16; kk++) {
            float a[4];
            a[0] = As[kk][ty*4+0]; a[1] = As[kk][ty*4+1];
            a[2] = As[kk][ty*4+2]; a[3] = As[kk][ty*4+3];
            float4 bv = *(float4*)&Bs[kk][tx*4];
            float b[4] = {bv.x, bv.y, bv.z, bv.w};
#pragma unroll
            for (int i = 0; i < 4; i++)
#pragma unroll
                for (int j = 0; j < 4; j++)
                    acc[i][j] += a[i] * b[j];
        }
        __syncthreads();
    }

    if (headsplit) {
        const int hh = n0 >> 6;   // head index
#pragma unroll
        for (int i = 0; i < 4; i++) {
            int m = m0 + ty*4 + i;
            int bb = m >> 10, s = m & 1023;
            float4 o = make_float4(acc[i][0], acc[i][1], acc[i][2], acc[i][3]);
            *(float4*)&out[((size_t)(bb*Hc + hh) * Sc + s) * DHc + tx*4] = o;
        }
    } else {
#pragma unroll
        for (int i = 0; i < 4; i++) {
            int m = m0 + ty*4 + i;
            float4 o = make_float4(acc[i][0], acc[i][1], acc[i][2], acc[i][3]);
            *(float4*)&out[(size_t)m * 512 + n0 + tx*4] = o;
        }
    }
}

// Merged 3-way projection: z selects (A, W, dst). 1536 CTAs -> full machine.
__global__ __launch_bounds__(256) void proj3(const float* __restrict__ A0,
                                             const float* __restrict__ A1,
                                             const float* __restrict__ A2,
                                             const float* __restrict__ W0,
                                             const float* __restrict__ W1,
                                             const float* __restrict__ W2,
                                             float* __restrict__ O0,
                                             float* __restrict__ O1,
                                             float* __restrict__ O2) {
    const int z = blockIdx.z;
    const float* A = (z == 0) ? A0 : (z == 1) ? A1 : A2;
    const float* W = (z == 0) ? W0 : (z == 1) ? W1 : W2;
    float*       O = (z == 0) ? O0 : (z == 1) ? O1 : O2;
    gemm512_body(A, W, O, 1);
}

__global__ __launch_bounds__(256) void gemm512(const float* __restrict__ A,
                                               const float* __restrict__ W,
                                               float* __restrict__ out,
                                               int headsplit) {
    gemm512_body(A, W, out, headsplit);
}

// ============================================================
// Fused causal attention with skewed relative bias.
// bias[j,t] = sum_d q[j,d] * R[h][d][S-1-j+t]   (t <= j)
// One CTA per (bh, 64-query tile), heavy tiles scheduled first.
// smem aliasing: kv = K (QK phase) then V (PV phase);
//                rp = R window (QK phase), ps lives inside rp (PV phase).
// 66 KB smem -> 3 CTAs/SM.
// ============================================================
__global__ __launch_bounds__(256, 3) void attn_kernel(const float* __restrict__ Rel) {
    extern __shared__ float sm[];
    float* qs = sm;                 // [d][j]  64x68   (persistent)
    float* kv = qs + 64*68;         // QK: K as [d][t] 64x68 ; PV: V as [t][d] 64x68
    float* rp = kv + 64*68;         // QK: R as [d][cc] 64x128 ; PV: ps as [t][j] 64x68

    const int tid = threadIdx.x;
    const int tx = tid & 15, ty = tid >> 4;
    const int bh = blockIdx.y;          // b*H + h
    const int h  = bh & (Hc-1);
    const int j0 = ((int)gridDim.x - 1 - (int)blockIdx.x) << 6;   // heavy first

    const float* Qp    = g_Q + ((size_t)bh * Sc + j0) * DHc;
    const float* Kbase = g_K + (size_t)bh * Sc * DHc;
    const float* Vbase = g_V + (size_t)bh * Sc * DHc;
    const float* Rp    = Rel + (size_t)h * DHc * Sc;

    // load Q tile -> qs[d][j]
    for (int f = tid; f < 1024; f += 256) {
        int j = f >> 4, d4 = (f & 15) << 2;
        float4 v = *(const float4*)(Qp + j*DHc + d4);
        qs[(d4+0)*68 + j] = v.x; qs[(d4+1)*68 + j] = v.y;
        qs[(d4+2)*68 + j] = v.z; qs[(d4+3)*68 + j] = v.w;
    }

    float mrow[4] = {-1e30f, -1e30f, -1e30f, -1e30f};
    float lrow[4] = {0.f, 0.f, 0.f, 0.f};
    float oacc[4][4] = {};

    const int base0 = 60 + 4*tx - 4*ty;   // r-window base: in [0,120], mult of 4
    const int ntiles = (j0 >> 6) + 1;

    for (int it = 0; it < ntiles; it++) {
        const int t0 = it << 6;
        __syncthreads();   // (a) prior PV reads of kv/rp done; qs visible on it==0

        // load K tile -> kv[d][t]
        for (int f = tid; f < 1024; f += 256) {
            int t = f >> 4, d4 = (f & 15) << 2;
            float4 k4 = *(const float4*)(Kbase + (size_t)(t0 + t)*DHc + d4);
            kv[(d4+0)*68 + t] = k4.x; kv[(d4+1)*68 + t] = k4.y;
            kv[(d4+2)*68 + t] = k4.z; kv[(d4+3)*68 + t] = k4.w;
        }
        // load R window: rp[d][cc] = R[d][cmin+cc], 127 cols used
        const int cmin = Sc - 64 - j0 + t0;   // >= 0, multiple of 4
        for (int f = tid; f < 64*32; f += 256) {
            int d = f >> 5, cc4 = (f & 31) << 2;
            int col = cmin + cc4;
            float4 rv4 = (col < Sc) ? *(const float4*)(Rp + (size_t)d*Sc + col)
                                    : make_float4(0.f, 0.f, 0.f, 0.f);
            *(float4*)(rp + d*128 + cc4) = rv4;
        }
        __syncthreads();   // (b)

        // s[j][t] = q.k + q.R[:, S-1-j+t]
        float acc[4][4] = {};
#pragma unroll 8
        for (int d = 0; d < 64; d++) {
            float4 qv = *(float4*)(qs + d*68 + ty*4);
            float4 k4 = *(float4*)(kv + d*68 + tx*4);
            float4 r0 = *(float4*)(rp + d*128 + base0);
            float4 r1 = *(float4*)(rp + d*128 + base0 + 4);
            float qa[4] = {qv.x, qv.y, qv.z, qv.w};
            float ka[4] = {k4.x, k4.y, k4.z, k4.w};
            float ra[8] = {r0.x, r0.y, r0.z, r0.w, r1.x, r1.y, r1.z, r1.w};
#pragma unroll
            for (int i = 0; i < 4; i++)
#pragma unroll
                for (int j = 0; j < 4; j++) {
                    acc[i][j] += qa[i] * ka[j];
                    acc[i][j] += qa[i] * ra[3 - i + j];   // c_local = 63-(jl)+(tl)
                }
        }

        // online softmax (scale AFTER bias+mask, matching reference);
        // p kept in acc registers until smem is safe to overwrite
#pragma unroll
        for (int i = 0; i < 4; i++) {
            const int j = j0 + ty*4 + i;
            float mx = -1e30f;
#pragma unroll
            for (int c = 0; c < 4; c++) {
                int t = t0 + tx*4 + c;
                float v = (t <= j) ? acc[i][c] * 0.125f : -1e30f;
                acc[i][c] = v;
                mx = fmaxf(mx, v);
            }
#pragma unroll
            for (int off = 8; off; off >>= 1)
                mx = fmaxf(mx, __shfl_xor_sync(0xffffffffu, mx, off, 16));
            float mnew = fmaxf(mrow[i], mx);
            float corr = __expf(mrow[i] - mnew);
            float ss = 0.f;
#pragma unroll
            for (int c = 0; c < 4; c++) {
                float p = __expf(acc[i][c] - mnew);
                acc[i][c] = p;
                ss += p;
            }
#pragma unroll
            for (int off = 8; off; off >>= 1)
                ss += __shfl_xor_sync(0xffffffffu, ss, off, 16);
            lrow[i] = lrow[i] * corr + ss;
            mrow[i] = mnew;
#pragma unroll
            for (int c = 0; c < 4; c++) oacc[i][c] *= corr;
        }
        __syncthreads();   // (c) all QK-phase reads of kv/rp complete

        // store p transposed: ps[t][j] (inside rp area), load V -> kv[t][d]
        float* ps = rp;
#pragma unroll
        for (int c = 0; c < 4; c++) {
            float4 pv = make_float4(acc[0][c], acc[1][c], acc[2][c], acc[3][c]);
            *(float4*)(ps + (tx*4 + c)*68 + ty*4) = pv;
        }
        for (int f = tid; f < 1024; f += 256) {
            int t = f >> 4, d4 = (f & 15) << 2;
            float4 vv = *(const float4*)(Vbase + (size_t)(t0 + t)*DHc + d4);
            *(float4*)(kv + t*68 + d4) = vv;
        }
        __syncthreads();   // (d)

        // O += P @ V   (p read is one LDS.128 per t now)
#pragma unroll 8
        for (int t = 0; t < 64; t++) {
            float4 vv = *(float4*)(kv + t*68 + tx*4);
            float4 p4 = *(float4*)(ps + t*68 + ty*4);
            float va[4] = {vv.x, vv.y, vv.z, vv.w};
            float pa[4] = {p4.x, p4.y, p4.z, p4.w};
#pragma unroll
            for (int i = 0; i < 4; i++)
#pragma unroll
                for (int c = 0; c < 4; c++)
                    oacc[i][c] += pa[i] * va[c];
        }
    }

    // epilogue: ctx[b][j][h*64 + dc]
    const int b = bh >> 3;
#pragma unroll
    for (int i = 0; i < 4; i++) {
        float inv = 1.f / lrow[i];
        float4 o = make_float4(oacc[i][0]*inv, oacc[i][1]*inv,
                               oacc[i][2]*inv, oacc[i][3]*inv);
        *(float4*)&g_ctx[((size_t)(b*Sc + j0 + ty*4 + i)) * Dc + h*DHc + tx*4] = o;
    }
}

// ============================================================
extern "C" void kernel_launch(void* const* d_in, const int* in_sizes, int n_in,
                              void* d_out, int out_size) {
    (void)in_sizes; (void)n_in; (void)out_size;
    const float* queries = (const float*)d_in[0];
    const float* keysp   = (const float*)d_in[1];
    const float* valuesp = (const float*)d_in[2];
    // d_in[3] = mask (causal; applied analytically)
    const float* Wq  = (const float*)d_in[4];
    const float* Wk  = (const float*)d_in[5];
    const float* Wv  = (const float*)d_in[6];
    const float* Wo  = (const float*)d_in[7];
    const float* rel = (const float*)d_in[8];
    float* out = (float*)d_out;

    float *pQ, *pK, *pV, *pC;
    cudaGetSymbolAddress((void**)&pQ, g_Q);
    cudaGetSymbolAddress((void**)&pK, g_K);
    cudaGetSymbolAddress((void**)&pV, g_V);
    cudaGetSymbolAddress((void**)&pC, g_ctx);

    const dim3 blk(256);

    // fused QKV projections: grid z selects which projection
    proj3<<<dim3(Dc/64, (Bc*Sc)/64, 3), blk>>>(queries, keysp, valuesp,
                                               Wq, Wk, Wv, pQ, pK, pV);

    const int smem = (2*64*68 + 64*128) * (int)sizeof(float);   // 67584 B -> 3 CTAs/SM
    cudaFuncSetAttribute(attn_kernel, cudaFuncAttributeMaxDynamicSharedMemorySize, smem);
    attn_kernel<<<dim3(Sc/64, Bc*Hc), blk, smem>>>(rel);

    gemm512<<<dim3(Dc/64, (Bc*Sc)/64), blk>>>(pC, Wo, out, 0);
}

// round 7
// speedup vs baseline: 1.1267x; 1.0856x over previous
#include <cuda_runtime.h>

#define Bc 4
#define Sc 1024
#define Dc 512
#define Hc 8
#define DHc 64

typedef unsigned long long u64;

// ---- f32x2 packed-math helpers (FFMA2 path: ptxas only emits via PTX) ----
__device__ __forceinline__ u64 ffma2(u64 a, u64 b, u64 c) {
    u64 d;
    asm("fma.rn.f32x2 %0, %1, %2, %3;" : "=l"(d) : "l"(a), "l"(b), "l"(c));
    return d;
}
__device__ __forceinline__ u64 fmul2(u64 a, u64 b) {
    u64 d;
    asm("mul.rn.f32x2 %0, %1, %2;" : "=l"(d) : "l"(a), "l"(b));
    return d;
}
__device__ __forceinline__ u64 pack2(float lo, float hi) {
    u64 d;
    asm("mov.b64 %0, {%1, %2};" : "=l"(d)
        : "r"(__float_as_uint(lo)), "r"(__float_as_uint(hi)));
    return d;
}
__device__ __forceinline__ u64 dup2(float x) { return pack2(x, x); }
__device__ __forceinline__ float2 unpk2(u64 v) {
    unsigned lo, hi;
    asm("mov.b64 {%0, %1}, %2;" : "=r"(lo), "=r"(hi) : "l"(v));
    return make_float2(__uint_as_float(lo), __uint_as_float(hi));
}

// ---- scratch (no allocations allowed) ----
__device__ float g_Q[Bc*Hc*Sc*DHc];   // [B,H,S,DH]
__device__ float g_K[Bc*Hc*Sc*DHc];
__device__ float g_V[Bc*Hc*Sc*DHc];
__device__ float g_ctx[Bc*Sc*Dc];     // [B,S,D]

// ============================================================
// GEMM: out = A[M,512] @ W[512,512]
// 128x128 block tile, 512 threads, 8(m)x4(n) per thread,
// f32x2 accumulators paired along M (a-operand = direct u64 LDS).
// ============================================================
__device__ __forceinline__ void gemm_body(const float* __restrict__ A,
                                          const float* __restrict__ W,
                                          float* __restrict__ out,
                                          int headsplit) {
    __shared__ float As[16][132];   // [k][m] transposed, stride mult of 4
    __shared__ float Bs[16][132];   // [k][n]
    const int tid = threadIdx.x;
    const int tx = tid & 31;        // n-group (cols tx*4..tx*4+3)
    const int ty = tid >> 5;        // m-group (rows ty*8..ty*8+7)
    const int m0 = blockIdx.y << 7, n0 = blockIdx.x << 7;

    const int ar = tid >> 2;            // 0..127 (A row)
    const int ac = (tid & 3) << 2;      // 0,4,8,12 (A col in k-slice)
    const int br = tid >> 5;            // 0..15  (B row = k)
    const int bc = (tid & 31) << 2;     // 0..124 (B col)

    u64 acc[4][4];                      // [m-pair][n]  (lo=row 2i, hi=row 2i+1)
#pragma unroll
    for (int i = 0; i < 4; i++)
#pragma unroll
        for (int j = 0; j < 4; j++) acc[i][j] = 0ull;

    for (int k0 = 0; k0 < 512; k0 += 16) {
        float4 av = *(const float4*)(A + (size_t)(m0 + ar) * 512 + k0 + ac);
        As[ac+0][ar] = av.x; As[ac+1][ar] = av.y;
        As[ac+2][ar] = av.z; As[ac+3][ar] = av.w;
        float4 wv = *(const float4*)(W + (size_t)(k0 + br) * 512 + n0 + bc);
        *(float4*)&Bs[br][bc] = wv;
        __syncthreads();
#pragma unroll
        for (int kk = 0; kk < 16; kk++) {
            ulonglong2 a01 = *(ulonglong2*)&As[kk][ty*8];
            ulonglong2 a23 = *(ulonglong2*)&As[kk][ty*8 + 4];
            float4 bv = *(float4*)&Bs[kk][tx*4];
            u64 a2[4] = { a01.x, a01.y, a23.x, a23.y };
            u64 b2[4] = { dup2(bv.x), dup2(bv.y), dup2(bv.z), dup2(bv.w) };
#pragma unroll
            for (int i = 0; i < 4; i++)
#pragma unroll
                for (int j = 0; j < 4; j++)
                    acc[i][j] = ffma2(a2[i], b2[j], acc[i][j]);
        }
        __syncthreads();
    }

    const int n = n0 + tx*4;
    if (headsplit) {
        const int hh = n >> 6;          // head index
        const int nc = n & 63;          // col within head
#pragma unroll
        for (int i = 0; i < 4; i++) {
            float2 c0 = unpk2(acc[i][0]), c1 = unpk2(acc[i][1]);
            float2 c2 = unpk2(acc[i][2]), c3 = unpk2(acc[i][3]);
            int m = m0 + ty*8 + 2*i;
            int bb = m >> 10, s = m & 1023;
            *(float4*)&out[((size_t)(bb*Hc + hh) * Sc + s) * DHc + nc] =
                make_float4(c0.x, c1.x, c2.x, c3.x);
            int m2 = m + 1, bb2 = m2 >> 10, s2 = m2 & 1023;
            *(float4*)&out[((size_t)(bb2*Hc + hh) * Sc + s2) * DHc + nc] =
                make_float4(c0.y, c1.y, c2.y, c3.y);
        }
    } else {
#pragma unroll
        for (int i = 0; i < 4; i++) {
            float2 c0 = unpk2(acc[i][0]), c1 = unpk2(acc[i][1]);
            float2 c2 = unpk2(acc[i][2]), c3 = unpk2(acc[i][3]);
            int m = m0 + ty*8 + 2*i;
            *(float4*)&out[(size_t)m * 512 + n] = make_float4(c0.x, c1.x, c2.x, c3.x);
            *(float4*)&out[(size_t)(m+1) * 512 + n] = make_float4(c0.y, c1.y, c2.y, c3.y);
        }
    }
}

// Merged 3-way projection: z selects (A, W, dst).
__global__ __launch_bounds__(512, 1) void proj3(const float* __restrict__ A0,
                                                const float* __restrict__ A1,
                                                const float* __restrict__ A2,
                                                const float* __restrict__ W0,
                                                const float* __restrict__ W1,
                                                const float* __restrict__ W2,
                                                float* __restrict__ O0,
                                                float* __restrict__ O1,
                                                float* __restrict__ O2) {
    const int z = blockIdx.z;
    const float* A = (z == 0) ? A0 : (z == 1) ? A1 : A2;
    const float* W = (z == 0) ? W0 : (z == 1) ? W1 : W2;
    float*       O = (z == 0) ? O0 : (z == 1) ? O1 : O2;
    gemm_body(A, W, O, 1);
}

__global__ __launch_bounds__(512, 1) void gemm512(const float* __restrict__ A,
                                                  const float* __restrict__ W,
                                                  float* __restrict__ out) {
    gemm_body(A, W, out, 0);
}

// ============================================================
// Fused causal attention with skewed relative bias (f32x2 math).
// bias[j,t] = sum_d q[j,d] * R[h][d][S-1-j+t]   (t <= j)
// smem aliasing: kv = K (QK phase) then V (PV phase);
//                rp = R window (QK phase), ps inside rp (PV phase).
// ============================================================
__global__ __launch_bounds__(256, 3) void attn_kernel(const float* __restrict__ Rel) {
    extern __shared__ float sm[];
    float* qs = sm;                 // [d][j]  64x68   (persistent)
    float* kv = qs + 64*68;         // QK: K as [d][t] ; PV: V as [t][d]
    float* rp = kv + 64*68;         // QK: R as [d][cc] 64x128 ; PV: ps as [t][j]

    const int tid = threadIdx.x;
    const int tx = tid & 15, ty = tid >> 4;
    const int bh = blockIdx.y;
    const int h  = bh & (Hc-1);
    const int j0 = ((int)gridDim.x - 1 - (int)blockIdx.x) << 6;   // heavy first

    const float* Qp    = g_Q + ((size_t)bh * Sc + j0) * DHc;
    const float* Kbase = g_K + (size_t)bh * Sc * DHc;
    const float* Vbase = g_V + (size_t)bh * Sc * DHc;
    const float* Rp    = Rel + (size_t)h * DHc * Sc;

    for (int f = tid; f < 1024; f += 256) {
        int j = f >> 4, d4 = (f & 15) << 2;
        float4 v = *(const float4*)(Qp + j*DHc + d4);
        qs[(d4+0)*68 + j] = v.x; qs[(d4+1)*68 + j] = v.y;
        qs[(d4+2)*68 + j] = v.z; qs[(d4+3)*68 + j] = v.w;
    }

    float mrow[4] = {-1e30f, -1e30f, -1e30f, -1e30f};
    float lrow[4] = {0.f, 0.f, 0.f, 0.f};
    u64 oacc2[4][2];                 // [j-row][t-col-pair along DH cols]
#pragma unroll
    for (int i = 0; i < 4; i++) { oacc2[i][0] = 0ull; oacc2[i][1] = 0ull; }

    const int base0 = 60 + 4*tx - 4*ty;   // in [0,120], mult of 4
    const int ntiles = (j0 >> 6) + 1;

    for (int it = 0; it < ntiles; it++) {
        const int t0 = it << 6;
        __syncthreads();   // (a)

        for (int f = tid; f < 1024; f += 256) {
            int t = f >> 4, d4 = (f & 15) << 2;
            float4 k4 = *(const float4*)(Kbase + (size_t)(t0 + t)*DHc + d4);
            kv[(d4+0)*68 + t] = k4.x; kv[(d4+1)*68 + t] = k4.y;
            kv[(d4+2)*68 + t] = k4.z; kv[(d4+3)*68 + t] = k4.w;
        }
        const int cmin = Sc - 64 - j0 + t0;   // >= 0, multiple of 4
        for (int f = tid; f < 64*32; f += 256) {
            int d = f >> 5, cc4 = (f & 31) << 2;
            int col = cmin + cc4;
            float4 rv4 = (col < Sc) ? *(const float4*)(Rp + (size_t)d*Sc + col)
                                    : make_float4(0.f, 0.f, 0.f, 0.f);
            *(float4*)(rp + d*128 + cc4) = rv4;
        }
        __syncthreads();   // (b)

        // s[j][t] = q.k + q.R[:, S-1-j+t]  -- f32x2, pairs along t
        u64 acc2[4][2];
#pragma unroll
        for (int i = 0; i < 4; i++) { acc2[i][0] = 0ull; acc2[i][1] = 0ull; }
#pragma unroll 8
        for (int d = 0; d < 64; d++) {
            float4 qv = *(float4*)(qs + d*68 + ty*4);
            ulonglong2 kk2 = *(ulonglong2*)(kv + d*68 + tx*4);
            float4 r0 = *(float4*)(rp + d*128 + base0);
            float4 r1 = *(float4*)(rp + d*128 + base0 + 4);
            u64 qa2[4] = { dup2(qv.x), dup2(qv.y), dup2(qv.z), dup2(qv.w) };
            // ra window f0..f7; pairs needed: even {f0f1,f2f3,f4f5}, odd {f1f2,f3f4,f5f6}
            u64 e0 = pack2(r0.x, r0.y), e1 = pack2(r0.z, r0.w), e2 = pack2(r1.x, r1.y);
            u64 o1 = pack2(r0.y, r0.z), o3 = pack2(r0.w, r1.x), o5 = pack2(r1.y, r1.z);
            // bias pair for (i, c-pair0) = {f[3-i],f[4-i]}, (i, c-pair1) = {f[5-i],f[6-i]}
            u64 rb00 = o3, rb01 = o5;   // i=0
            u64 rb10 = e1, rb11 = e2;   // i=1
            u64 rb20 = o1, rb21 = o3;   // i=2
            u64 rb30 = e0, rb31 = e1;   // i=3
            acc2[0][0] = ffma2(qa2[0], kk2.x, acc2[0][0]);
            acc2[0][1] = ffma2(qa2[0], kk2.y, acc2[0][1]);
            acc2[0][0] = ffma2(qa2[0], rb00,  acc2[0][0]);
            acc2[0][1] = ffma2(qa2[0], rb01,  acc2[0][1]);
            acc2[1][0] = ffma2(qa2[1], kk2.x, acc2[1][0]);
            acc2[1][1] = ffma2(qa2[1], kk2.y, acc2[1][1]);
            acc2[1][0] = ffma2(qa2[1], rb10,  acc2[1][0]);
            acc2[1][1] = ffma2(qa2[1], rb11,  acc2[1][1]);
            acc2[2][0] = ffma2(qa2[2], kk2.x, acc2[2][0]);
            acc2[2][1] = ffma2(qa2[2], kk2.y, acc2[2][1]);
            acc2[2][0] = ffma2(qa2[2], rb20,  acc2[2][0]);
            acc2[2][1] = ffma2(qa2[2], rb21,  acc2[2][1]);
            acc2[3][0] = ffma2(qa2[3], kk2.x, acc2[3][0]);
            acc2[3][1] = ffma2(qa2[3], kk2.y, acc2[3][1]);
            acc2[3][0] = ffma2(qa2[3], rb30,  acc2[3][0]);
            acc2[3][1] = ffma2(qa2[3], rb31,  acc2[3][1]);
        }

        // unpack to scalars for softmax
        float acc[4][4];
#pragma unroll
        for (int i = 0; i < 4; i++) {
            float2 u0 = unpk2(acc2[i][0]), u1 = unpk2(acc2[i][1]);
            acc[i][0] = u0.x; acc[i][1] = u0.y; acc[i][2] = u1.x; acc[i][3] = u1.y;
        }

        // online softmax (scale AFTER bias+mask, matching reference)
#pragma unroll
        for (int i = 0; i < 4; i++) {
            const int j = j0 + ty*4 + i;
            float mx = -1e30f;
#pragma unroll
            for (int c = 0; c < 4; c++) {
                int t = t0 + tx*4 + c;
                float v = (t <= j) ? acc[i][c] * 0.125f : -1e30f;
                acc[i][c] = v;
                mx = fmaxf(mx, v);
            }
#pragma unroll
            for (int off = 8; off; off >>= 1)
                mx = fmaxf(mx, __shfl_xor_sync(0xffffffffu, mx, off, 16));
            float mnew = fmaxf(mrow[i], mx);
            float corr = __expf(mrow[i] - mnew);
            float ss = 0.f;
#pragma unroll
            for (int c = 0; c < 4; c++) {
                float p = __expf(acc[i][c] - mnew);
                acc[i][c] = p;
                ss += p;
            }
#pragma unroll
            for (int off = 8; off; off >>= 1)
                ss += __shfl_xor_sync(0xffffffffu, ss, off, 16);
            lrow[i] = lrow[i] * corr + ss;
            mrow[i] = mnew;
            u64 corr2 = dup2(corr);
            oacc2[i][0] = fmul2(oacc2[i][0], corr2);
            oacc2[i][1] = fmul2(oacc2[i][1], corr2);
        }
        __syncthreads();   // (c)

        // store p transposed: ps[t][j] (inside rp), load V -> kv[t][d]
        float* ps = rp;
#pragma unroll
        for (int c = 0; c < 4; c++) {
            float4 pv = make_float4(acc[0][c], acc[1][c], acc[2][c], acc[3][c]);
            *(float4*)(ps + (tx*4 + c)*68 + ty*4) = pv;
        }
        for (int f = tid; f < 1024; f += 256) {
            int t = f >> 4, d4 = (f & 15) << 2;
            float4 vv = *(const float4*)(Vbase + (size_t)(t0 + t)*DHc + d4);
            *(float4*)(kv + t*68 + d4) = vv;
        }
        __syncthreads();   // (d)

        // O += P @ V  (f32x2, pairs along DH cols)
#pragma unroll 8
        for (int t = 0; t < 64; t++) {
            ulonglong2 vv2 = *(ulonglong2*)(kv + t*68 + tx*4);
            float4 p4 = *(float4*)(ps + t*68 + ty*4);
            u64 pa0 = dup2(p4.x), pa1 = dup2(p4.y), pa2v = dup2(p4.z), pa3 = dup2(p4.w);
            oacc2[0][0] = ffma2(pa0,  vv2.x, oacc2[0][0]);
            oacc2[0][1] = ffma2(pa0,  vv2.y, oacc2[0][1]);
            oacc2[1][0] = ffma2(pa1,  vv2.x, oacc2[1][0]);
            oacc2[1][1] = ffma2(pa1,  vv2.y, oacc2[1][1]);
            oacc2[2][0] = ffma2(pa2v, vv2.x, oacc2[2][0]);
            oacc2[2][1] = ffma2(pa2v, vv2.y, oacc2[2][1]);
            oacc2[3][0] = ffma2(pa3,  vv2.x, oacc2[3][0]);
            oacc2[3][1] = ffma2(pa3,  vv2.y, oacc2[3][1]);
        }
    }

    // epilogue: ctx[b][j][h*64 + dc]
    const int b = bh >> 3;
#pragma unroll
    for (int i = 0; i < 4; i++) {
        float inv = 1.f / lrow[i];
        float2 u0 = unpk2(oacc2[i][0]), u1 = unpk2(oacc2[i][1]);
        float4 o = make_float4(u0.x*inv, u0.y*inv, u1.x*inv, u1.y*inv);
        *(float4*)&g_ctx[((size_t)(b*Sc + j0 + ty*4 + i)) * Dc + h*DHc + tx*4] = o;
    }
}

// ============================================================
extern "C" void kernel_launch(void* const* d_in, const int* in_sizes, int n_in,
                              void* d_out, int out_size) {
    (void)in_sizes; (void)n_in; (void)out_size;
    const float* queries = (const float*)d_in[0];
    const float* keysp   = (const float*)d_in[1];
    const float* valuesp = (const float*)d_in[2];
    // d_in[3] = mask (causal; applied analytically)
    const float* Wq  = (const float*)d_in[4];
    const float* Wk  = (const float*)d_in[5];
    const float* Wv  = (const float*)d_in[6];
    const float* Wo  = (const float*)d_in[7];
    const float* rel = (const float*)d_in[8];
    float* out = (float*)d_out;

    float *pQ, *pK, *pV, *pC;
    cudaGetSymbolAddress((void**)&pQ, g_Q);
    cudaGetSymbolAddress((void**)&pK, g_K);
    cudaGetSymbolAddress((void**)&pV, g_V);
    cudaGetSymbolAddress((void**)&pC, g_ctx);

    // fused QKV projections: 128x128 tiles, z selects projection
    proj3<<<dim3(Dc/128, (Bc*Sc)/128, 3), 512>>>(queries, keysp, valuesp,
                                                 Wq, Wk, Wv, pQ, pK, pV);

    const int smem = (2*64*68 + 64*128) * (int)sizeof(float);   // 67584 B -> 3 CTAs/SM
    cudaFuncSetAttribute(attn_kernel, cudaFuncAttributeMaxDynamicSharedMemorySize, smem);
    attn_kernel<<<dim3(Sc/64, Bc*Hc), 256, smem>>>(rel);

    gemm512<<<dim3(Dc/128, (Bc*Sc)/128), 512>>>(pC, Wo, out);
}